// round 2
// baseline (speedup 1.0000x reference)
#include <cuda_runtime.h>

#define BB 2
#define CC 64
#define DD 48
#define HH 48
#define WW 48
#define HW (HH*WW)          // 2304
#define DHW (DD*HW)         // 110592
#define TOT (BB*CC*DHW)     // 14155776

typedef unsigned long long u64;

__device__ float g_t1[TOT];
__device__ float g_t2[TOT];

// ---- packed f32x2 helpers (Blackwell FFMA2 path) -------------------------
__device__ __forceinline__ u64 pk(float lo, float hi) {
    u64 r; asm("mov.b64 %0,{%1,%2};" : "=l"(r) : "f"(lo), "f"(hi)); return r;
}
__device__ __forceinline__ void upk(u64 v, float& lo, float& hi) {
    asm("mov.b64 {%0,%1},%2;" : "=f"(lo), "=f"(hi) : "l"(v));
}
__device__ __forceinline__ u64 ffma2(u64 a, u64 b, u64 c) {
    u64 d; asm("fma.rn.f32x2 %0,%1,%2,%3;" : "=l"(d) : "l"(a), "l"(b), "l"(c));
    return d;
}

// ---------------------------------------------------------------------------
// Kernel 1: depthwise 5x5x5, pad 2.  x -> g_t1
// Block tile: 8z x 8y x 48w. 96 threads = 8ty x 3wg x 4zg.
// Thread: 2z x 16w outputs as 8 f32x2 pairs per z. Rows read as LDS.128.
// Smem: 12 x 12 x 60 (stride 60 -> conflict-free LDS.128 phases).
// ---------------------------------------------------------------------------
#define S5 60
__global__ __launch_bounds__(96) void dw5_kernel(
    const float* __restrict__ x,
    const float* __restrict__ w0,
    const float* __restrict__ b0)
{
    __shared__ float  sh[12 * 12 * S5];
    __shared__ float2 sw2[125];

    const int z0b = blockIdx.x * 8;
    const int y0  = blockIdx.y * 8;
    const int bc  = blockIdx.z;
    const int c   = bc & 63;
    const int tid = threadIdx.x;

    const float* __restrict__ xin = x + (size_t)bc * DHW;

    for (int i = tid; i < 125; i += 96) {
        float w = w0[c * 125 + i];
        sw2[i] = make_float2(w, w);
    }
    for (int idx = tid; idx < 12 * 12 * S5; idx += 96) {
        int p  = idx / (12 * S5);
        int r  = idx % (12 * S5);
        int yi = r / S5;
        int wi = r % S5;
        int gz = z0b - 2 + p, gy = y0 - 2 + yi, gw = wi - 2;
        float v = 0.f;
        if ((unsigned)gz < 48u && (unsigned)gy < 48u && (unsigned)gw < 48u)
            v = xin[gz * HW + gy * WW + gw];
        sh[idx] = v;
    }
    __syncthreads();

    const int ty    = tid & 7;
    const int rest  = tid >> 3;
    const int wg    = rest % 3;
    const int zg    = rest / 3;        // 0..3
    const int wbase = wg * 16;

    u64 acc0[8], acc1[8];
    #pragma unroll
    for (int j = 0; j < 8; ++j) { acc0[j] = 0ull; acc1[j] = 0ull; }

    #pragma unroll 1
    for (int dy = 0; dy < 5; ++dy) {
        u64 wb[2][5];
        #pragma unroll
        for (int st = 0; st < 6; ++st) {
            const float4* row4 =
                (const float4*)&sh[((zg * 2 + st) * 12 + ty + dy) * S5 + wbase];
            float4 q0 = row4[0], q1 = row4[1], q2 = row4[2], q3 = row4[3], q4 = row4[4];
            float v[20] = {q0.x,q0.y,q0.z,q0.w, q1.x,q1.y,q1.z,q1.w,
                           q2.x,q2.y,q2.z,q2.w, q3.x,q3.y,q3.z,q3.w,
                           q4.x,q4.y,q4.z,q4.w};
            u64 pe[10], po[9];
            #pragma unroll
            for (int i = 0; i < 10; ++i) pe[i] = pk(v[2 * i], v[2 * i + 1]);
            #pragma unroll
            for (int i = 0; i < 9; ++i)  po[i] = pk(v[2 * i + 1], v[2 * i + 2]);

            u64* wn = wb[st & 1];
            u64* wp = wb[(st & 1) ^ 1];

            if (st <= 4) {                       // loz=0: dz = st
                const u64* wr = (const u64*)&sw2[(st * 5 + dy) * 5];
                #pragma unroll
                for (int dw = 0; dw < 5; ++dw) wn[dw] = wr[dw];
                #pragma unroll
                for (int dw = 0; dw < 5; ++dw) {
                    const u64 w = wn[dw];
                    #pragma unroll
                    for (int j = 0; j < 8; ++j) {
                        const int s = 2 * j + dw;
                        acc0[j] = ffma2(w, (dw & 1) ? po[s >> 1] : pe[s >> 1], acc0[j]);
                    }
                }
            }
            if (st >= 1) {                       // loz=1: dz = st-1 (rotated weights)
                #pragma unroll
                for (int dw = 0; dw < 5; ++dw) {
                    const u64 w = wp[dw];
                    #pragma unroll
                    for (int j = 0; j < 8; ++j) {
                        const int s = 2 * j + dw;
                        acc1[j] = ffma2(w, (dw & 1) ? po[s >> 1] : pe[s >> 1], acc1[j]);
                    }
                }
            }
        }
    }

    const float bias = __ldg(&b0[c]);
    float* __restrict__ ob = g_t1 + (size_t)bc * DHW;
    #pragma unroll
    for (int loz = 0; loz < 2; ++loz) {
        const u64* a = loz ? acc1 : acc0;
        const int gz = z0b + zg * 2 + loz;
        float4* op = (float4*)(ob + gz * HW + (y0 + ty) * WW + wbase);
        #pragma unroll
        for (int k = 0; k < 4; ++k) {
            float l0, h0, l1, h1;
            upk(a[2 * k], l0, h0);
            upk(a[2 * k + 1], l1, h1);
            op[k] = make_float4(l0 + bias, h0 + bias, l1 + bias, h1 + bias);
        }
    }
}

// ---------------------------------------------------------------------------
// Kernel 2: depthwise 7x7x7, dilation 3, pad 9.  g_t1 -> g_t2
// Residue decomposition into 27 dense 16^3 subgrids (7^3 pad-3 conv each).
// Block: (res*2+zhalf, c, b); 64 threads = 16ty x 4zg; thread: 2z x 16w.
// Smem: 14 x 22 x 28 (stride 28 -> conflict-free LDS.128 phases).
// ---------------------------------------------------------------------------
#define S7 28
__global__ __launch_bounds__(64) void dw7_kernel(
    const float* __restrict__ ws,
    const float* __restrict__ bs)
{
    __shared__ float  sh[14 * 22 * S7];
    __shared__ float2 sw2[343];

    const int bx    = blockIdx.x;
    const int zhalf = bx & 1;
    const int res   = bx >> 1;
    const int rz = res / 9, ry = (res / 3) % 3, rw = res % 3;
    const int c  = blockIdx.y;
    const int b  = blockIdx.z;
    const int bc = b * 64 + c;
    const int tid = threadIdx.x;

    const float* __restrict__ xin = g_t1 + (size_t)bc * DHW;

    for (int i = tid; i < 343; i += 64) {
        float w = ws[c * 343 + i];
        sw2[i] = make_float2(w, w);
    }
    const int zb = zhalf * 8;
    for (int idx = tid; idx < 14 * 22 * S7; idx += 64) {
        int p  = idx / (22 * S7);
        int r  = idx % (22 * S7);
        int yi = r / S7;
        int wi = r % S7;
        int sz = zb - 3 + p, sy = yi - 3, sx = wi - 3;
        float v = 0.f;
        if ((unsigned)sz < 16u && (unsigned)sy < 16u && (unsigned)sx < 16u)
            v = xin[(3 * sz + rz) * HW + (3 * sy + ry) * WW + (3 * sx + rw)];
        sh[idx] = v;
    }
    __syncthreads();

    const int ty = tid & 15;
    const int zg = tid >> 4;           // 0..3

    u64 acc0[8], acc1[8];
    #pragma unroll
    for (int j = 0; j < 8; ++j) { acc0[j] = 0ull; acc1[j] = 0ull; }

    #pragma unroll 1
    for (int dy = 0; dy < 7; ++dy) {
        u64 wb[2][7];
        #pragma unroll
        for (int st = 0; st < 8; ++st) {
            const float4* row4 =
                (const float4*)&sh[((zg * 2 + st) * 22 + ty + dy) * S7];
            float4 q0 = row4[0], q1 = row4[1], q2 = row4[2],
                   q3 = row4[3], q4 = row4[4], q5 = row4[5];
            float v[22] = {q0.x,q0.y,q0.z,q0.w, q1.x,q1.y,q1.z,q1.w,
                           q2.x,q2.y,q2.z,q2.w, q3.x,q3.y,q3.z,q3.w,
                           q4.x,q4.y,q4.z,q4.w, q5.x,q5.y};
            u64 pe[11], po[10];
            #pragma unroll
            for (int i = 0; i < 11; ++i) pe[i] = pk(v[2 * i], v[2 * i + 1]);
            #pragma unroll
            for (int i = 0; i < 10; ++i) po[i] = pk(v[2 * i + 1], v[2 * i + 2]);

            u64* wn = wb[st & 1];
            u64* wp = wb[(st & 1) ^ 1];

            if (st <= 6) {                      // loz=0: dz = st
                const u64* wr = (const u64*)&sw2[(st * 7 + dy) * 7];
                #pragma unroll
                for (int dw = 0; dw < 7; ++dw) wn[dw] = wr[dw];
                #pragma unroll
                for (int dw = 0; dw < 7; ++dw) {
                    const u64 w = wn[dw];
                    #pragma unroll
                    for (int j = 0; j < 8; ++j) {
                        const int s = 2 * j + dw;
                        acc0[j] = ffma2(w, (dw & 1) ? po[s >> 1] : pe[s >> 1], acc0[j]);
                    }
                }
            }
            if (st >= 1) {                      // loz=1: dz = st-1 (rotated weights)
                #pragma unroll
                for (int dw = 0; dw < 7; ++dw) {
                    const u64 w = wp[dw];
                    #pragma unroll
                    for (int j = 0; j < 8; ++j) {
                        const int s = 2 * j + dw;
                        acc1[j] = ffma2(w, (dw & 1) ? po[s >> 1] : pe[s >> 1], acc1[j]);
                    }
                }
            }
        }
    }

    const float bias = __ldg(&bs[c]);
    float* __restrict__ ob = g_t2 + (size_t)bc * DHW;
    #pragma unroll
    for (int loz = 0; loz < 2; ++loz) {
        const u64* a  = loz ? acc1 : acc0;
        const int gz = 3 * (zb + zg * 2 + loz) + rz;
        const int gy = 3 * ty + ry;
        float* op = ob + gz * HW + gy * WW + rw;
        #pragma unroll
        for (int j = 0; j < 8; ++j) {
            float lo, hi;
            upk(a[j], lo, hi);
            op[3 * (2 * j)]     = lo + bias;
            op[3 * (2 * j + 1)] = hi + bias;
        }
    }
}

// ---------------------------------------------------------------------------
// Kernel 3: pointwise 64x64 conv + bias + gate by x.  g_t2, x -> out
// Block: 256 spatial points x 64 co. 256 threads = 32 pg (8 pts) x 8 cg (8 co).
// FFMA2 over point pairs; W broadcast from smem; t2 reused 8x via L1.
// ---------------------------------------------------------------------------
__global__ __launch_bounds__(256) void pw_kernel(
    const float* __restrict__ x,
    const float* __restrict__ w1,
    const float* __restrict__ b1,
    float* __restrict__ out)
{
    __shared__ float sW[64 * 64];

    const int p0  = blockIdx.x * 256;
    const int b   = blockIdx.y;
    const int tid = threadIdx.x;

    for (int i = tid; i < 4096; i += 256) sW[i] = w1[i];
    __syncthreads();

    const int pg = tid & 31;      // 32 groups of 8 points
    const int cg = tid >> 5;      // 8 groups of 8 out-channels

    u64 acc[8][4];
    #pragma unroll
    for (int j = 0; j < 8; ++j)
        #pragma unroll
        for (int k = 0; k < 4; ++k) acc[j][k] = 0ull;

    const float4* __restrict__ tp =
        (const float4*)(g_t2 + (size_t)b * 64 * DHW + p0) + pg * 2;

    #pragma unroll 4
    for (int ci = 0; ci < 64; ++ci) {
        const float4 A  = __ldg(tp + (size_t)ci * (DHW / 4));
        const float4 Bv = __ldg(tp + (size_t)ci * (DHW / 4) + 1);
        const u64 v0 = pk(A.x, A.y),  v1 = pk(A.z, A.w);
        const u64 v2 = pk(Bv.x, Bv.y), v3 = pk(Bv.z, Bv.w);
        const float* __restrict__ wr = &sW[ci];
        #pragma unroll
        for (int j = 0; j < 8; ++j) {
            const float wv = wr[(cg * 8 + j) * 64];
            const u64 w2 = pk(wv, wv);
            acc[j][0] = ffma2(w2, v0, acc[j][0]);
            acc[j][1] = ffma2(w2, v1, acc[j][1]);
            acc[j][2] = ffma2(w2, v2, acc[j][2]);
            acc[j][3] = ffma2(w2, v3, acc[j][3]);
        }
    }

    #pragma unroll
    for (int j = 0; j < 8; ++j) {
        const int co = cg * 8 + j;
        const float bias = __ldg(&b1[co]);
        const size_t off = (size_t)(b * 64 + co) * DHW + p0 + pg * 8;
        const float4 xa = __ldg((const float4*)(x + off));
        const float4 xb = __ldg((const float4*)(x + off + 4));
        float a0,a1,a2,a3,a4,a5,a6,a7;
        upk(acc[j][0], a0, a1); upk(acc[j][1], a2, a3);
        upk(acc[j][2], a4, a5); upk(acc[j][3], a6, a7);
        float4 o0 = make_float4(xa.x*(a0+bias), xa.y*(a1+bias),
                                xa.z*(a2+bias), xa.w*(a3+bias));
        float4 o1 = make_float4(xb.x*(a4+bias), xb.y*(a5+bias),
                                xb.z*(a6+bias), xb.w*(a7+bias));
        *(float4*)(out + off)     = o0;
        *(float4*)(out + off + 4) = o1;
    }
}

// ---------------------------------------------------------------------------
extern "C" void kernel_launch(void* const* d_in, const int* in_sizes, int n_in,
                              void* d_out, int out_size)
{
    const float* x  = (const float*)d_in[0];
    const float* w0 = (const float*)d_in[1];
    const float* b0 = (const float*)d_in[2];
    const float* ws = (const float*)d_in[3];
    const float* bs = (const float*)d_in[4];
    const float* w1 = (const float*)d_in[5];
    const float* b1 = (const float*)d_in[6];
    float* out = (float*)d_out;

    dw5_kernel<<<dim3(6, 6, BB * CC), 96>>>(x, w0, b0);
    dw7_kernel<<<dim3(54, CC, BB), 64>>>(ws, bs);
    pw_kernel<<<dim3(DHW / 256, BB), 256>>>(x, w1, b1, out);
}

// round 3
// speedup vs baseline: 1.2513x; 1.2513x over previous
#include <cuda_runtime.h>

#define BB 2
#define CC 64
#define DD 48
#define HH 48
#define WW 48
#define HW (HH*WW)          // 2304
#define DHW (DD*HW)         // 110592
#define TOT (BB*CC*DHW)     // 14155776

__device__ float g_t1[TOT];
__device__ float g_t2[TOT];

// ---------------------------------------------------------------------------
// Kernel 1: depthwise 5x5x5, pad 2.  x -> g_t1
// Block tile: 8z x 8y x 48w. 192 threads = 8ty x 6wg x 4zg.
// Thread: 2z x 8w outputs, scalar FFMA. Rows read as 3x LDS.128.
// Smem: 12 x 12 x 60 floats (stride 60 = odd*4 quads -> conflict-free).
// Weight rows register-rotated across st (z-plane) steps.
// ---------------------------------------------------------------------------
#define S5 60
__global__ __launch_bounds__(192) void dw5_kernel(
    const float* __restrict__ x,
    const float* __restrict__ w0,
    const float* __restrict__ b0)
{
    __shared__ float sh[12 * 12 * S5];   // 34560 B
    __shared__ float sw[125];

    const int z0b = blockIdx.x * 8;
    const int y0  = blockIdx.y * 8;
    const int bc  = blockIdx.z;
    const int c   = bc & 63;
    const int tid = threadIdx.x;

    const float* __restrict__ xin = x + (size_t)bc * DHW;

    if (tid < 125) sw[tid] = w0[c * 125 + tid];

    for (int idx = tid; idx < 12 * 12 * S5; idx += 192) {
        int zi = idx / (12 * S5);
        int r  = idx % (12 * S5);
        int yi = r / S5;
        int wi = r % S5;
        int gz = z0b - 2 + zi, gy = y0 - 2 + yi, gw = wi - 2;
        float v = 0.f;
        if ((unsigned)gz < 48u && (unsigned)gy < 48u && (unsigned)gw < 48u)
            v = xin[gz * HW + gy * WW + gw];
        sh[idx] = v;
    }
    __syncthreads();

    const int ty    = tid & 7;
    const int wg    = (tid >> 3) % 6;
    const int zg    = tid / 48;          // 0..3
    const int wbase = wg * 8;

    const float bias = __ldg(&b0[c]);
    float acc0[8], acc1[8];
    #pragma unroll
    for (int j = 0; j < 8; ++j) { acc0[j] = bias; acc1[j] = bias; }

    #pragma unroll 1
    for (int dy = 0; dy < 5; ++dy) {
        float wb[2][5];
        #pragma unroll
        for (int st = 0; st < 6; ++st) {
            const float4* row4 =
                (const float4*)&sh[((zg * 2 + st) * 12 + ty + dy) * S5 + wbase];
            float4 q0 = row4[0], q1 = row4[1], q2 = row4[2];
            float v[12] = {q0.x,q0.y,q0.z,q0.w, q1.x,q1.y,q1.z,q1.w,
                           q2.x,q2.y,q2.z,q2.w};

            float* wn = wb[st & 1];
            float* wp = wb[(st & 1) ^ 1];

            if (st <= 4) {                       // loz=0: dz = st
                const float* __restrict__ wr = &sw[(st * 5 + dy) * 5];
                #pragma unroll
                for (int dw = 0; dw < 5; ++dw) wn[dw] = wr[dw];
                #pragma unroll
                for (int dw = 0; dw < 5; ++dw) {
                    const float w = wn[dw];
                    #pragma unroll
                    for (int k = 0; k < 8; ++k)
                        acc0[k] += w * v[k + dw];
                }
            }
            if (st >= 1) {                       // loz=1: dz = st-1 (rotated)
                #pragma unroll
                for (int dw = 0; dw < 5; ++dw) {
                    const float w = wp[dw];
                    #pragma unroll
                    for (int k = 0; k < 8; ++k)
                        acc1[k] += w * v[k + dw];
                }
            }
        }
    }

    float* __restrict__ ob = g_t1 + (size_t)bc * DHW;
    #pragma unroll
    for (int loz = 0; loz < 2; ++loz) {
        const float* a = loz ? acc1 : acc0;
        const int gz = z0b + zg * 2 + loz;
        float4* op = (float4*)(ob + gz * HW + (y0 + ty) * WW + wbase);
        op[0] = make_float4(a[0], a[1], a[2], a[3]);
        op[1] = make_float4(a[4], a[5], a[6], a[7]);
    }
}

// ---------------------------------------------------------------------------
// Kernel 2: depthwise 7x7x7, dilation 3, pad 9.  g_t1 -> g_t2
// Residue decomposition into 27 dense 16^3 subgrids (7^3 pad-3 conv each).
// Block: (res*2+zhalf, c, b); 128 threads = 16ty x 2wg x 4zg.
// Thread: 2z x 8w outputs, scalar FFMA. Rows read as 4x LDS.128.
// Smem: 14 x 22 x 28 floats (stride 28 = odd*7 quads -> conflict-free).
// ---------------------------------------------------------------------------
#define S7 28
__global__ __launch_bounds__(128) void dw7_kernel(
    const float* __restrict__ ws,
    const float* __restrict__ bs)
{
    __shared__ float sh[14 * 22 * S7];   // 34496 B
    __shared__ float sw[343];

    const int bx    = blockIdx.x;
    const int zhalf = bx & 1;
    const int res   = bx >> 1;
    const int rz = res / 9, ry = (res / 3) % 3, rw = res % 3;
    const int c  = blockIdx.y;
    const int b  = blockIdx.z;
    const int bc = b * 64 + c;
    const int tid = threadIdx.x;

    const float* __restrict__ xin = g_t1 + (size_t)bc * DHW;

    for (int i = tid; i < 343; i += 128) sw[i] = ws[c * 343 + i];

    const int zb = zhalf * 8;
    for (int idx = tid; idx < 14 * 22 * S7; idx += 128) {
        int zi = idx / (22 * S7);
        int r  = idx % (22 * S7);
        int yi = r / S7;
        int wi = r % S7;
        int sz = zb - 3 + zi, sy = yi - 3, sx = wi - 3;
        float v = 0.f;
        if ((unsigned)sz < 16u && (unsigned)sy < 16u && (unsigned)sx < 16u)
            v = xin[(3 * sz + rz) * HW + (3 * sy + ry) * WW + (3 * sx + rw)];
        sh[idx] = v;
    }
    __syncthreads();

    const int ty    = tid & 15;
    const int wg    = (tid >> 4) & 1;
    const int zg    = tid >> 5;          // 0..3
    const int wbase = wg * 8;

    const float bias = __ldg(&bs[c]);
    float acc0[8], acc1[8];
    #pragma unroll
    for (int j = 0; j < 8; ++j) { acc0[j] = bias; acc1[j] = bias; }

    #pragma unroll 1
    for (int dy = 0; dy < 7; ++dy) {
        float wb[2][7];
        #pragma unroll
        for (int st = 0; st < 8; ++st) {
            const float4* row4 =
                (const float4*)&sh[((zg * 2 + st) * 22 + ty + dy) * S7 + wbase];
            float4 q0 = row4[0], q1 = row4[1], q2 = row4[2], q3 = row4[3];
            float v[16] = {q0.x,q0.y,q0.z,q0.w, q1.x,q1.y,q1.z,q1.w,
                           q2.x,q2.y,q2.z,q2.w, q3.x,q3.y,q3.z,q3.w};

            float* wn = wb[st & 1];
            float* wp = wb[(st & 1) ^ 1];

            if (st <= 6) {                      // loz=0: dz = st
                const float* __restrict__ wr = &sw[(st * 7 + dy) * 7];
                #pragma unroll
                for (int dw = 0; dw < 7; ++dw) wn[dw] = wr[dw];
                #pragma unroll
                for (int dw = 0; dw < 7; ++dw) {
                    const float w = wn[dw];
                    #pragma unroll
                    for (int k = 0; k < 8; ++k)
                        acc0[k] += w * v[k + dw];
                }
            }
            if (st >= 1) {                      // loz=1: dz = st-1 (rotated)
                #pragma unroll
                for (int dw = 0; dw < 7; ++dw) {
                    const float w = wp[dw];
                    #pragma unroll
                    for (int k = 0; k < 8; ++k)
                        acc1[k] += w * v[k + dw];
                }
            }
        }
    }

    float* __restrict__ ob = g_t2 + (size_t)bc * DHW;
    #pragma unroll
    for (int loz = 0; loz < 2; ++loz) {
        const float* a = loz ? acc1 : acc0;
        const int gz = 3 * (zb + zg * 2 + loz) + rz;
        const int gy = 3 * ty + ry;
        float* op = ob + gz * HW + gy * WW + rw;
        #pragma unroll
        for (int j = 0; j < 8; ++j)
            op[3 * (wbase + j)] = a[j];
    }
}

// ---------------------------------------------------------------------------
// Kernel 3: pointwise 64x64 conv + bias + gate by x.  g_t2, x -> out
// Block: 128 spatial points x 64 co. 256 threads = 16 pg (8 pts) x 16 cg (4 co).
// Weights transposed in smem: one LDS.128 per ci yields 4 co-weights.
// Per ci iter: 2 LDG.128 + 1 LDS.128 + 32 FFMA.
// ---------------------------------------------------------------------------
__global__ __launch_bounds__(256) void pw_kernel(
    const float* __restrict__ x,
    const float* __restrict__ w1,
    const float* __restrict__ b1,
    float* __restrict__ out)
{
    __shared__ float sWt[64 * 64];       // [ci][co]

    const int p0  = blockIdx.x * 128;
    const int b   = blockIdx.y;
    const int tid = threadIdx.x;

    for (int i = tid; i < 4096; i += 256) {
        int co = i >> 6, ci = i & 63;
        sWt[ci * 64 + co] = w1[i];
    }
    __syncthreads();

    const int pg = tid & 15;      // 16 groups of 8 points
    const int cg = tid >> 4;      // 16 groups of 4 out-channels

    float acc[4][8];
    #pragma unroll
    for (int j = 0; j < 4; ++j) {
        const float bias = __ldg(&b1[cg * 4 + j]);
        #pragma unroll
        for (int k = 0; k < 8; ++k) acc[j][k] = bias;
    }

    const float4* __restrict__ tp =
        (const float4*)(g_t2 + (size_t)b * 64 * DHW + p0) + pg * 2;

    #pragma unroll 4
    for (int ci = 0; ci < 64; ++ci) {
        const float4 A = __ldg(tp + (size_t)ci * (DHW / 4));
        const float4 B = __ldg(tp + (size_t)ci * (DHW / 4) + 1);
        const float4 wv = *(const float4*)&sWt[ci * 64 + cg * 4];
        const float w4[4] = {wv.x, wv.y, wv.z, wv.w};
        #pragma unroll
        for (int j = 0; j < 4; ++j) {
            const float w = w4[j];
            acc[j][0] += w * A.x;  acc[j][1] += w * A.y;
            acc[j][2] += w * A.z;  acc[j][3] += w * A.w;
            acc[j][4] += w * B.x;  acc[j][5] += w * B.y;
            acc[j][6] += w * B.z;  acc[j][7] += w * B.w;
        }
    }

    #pragma unroll
    for (int j = 0; j < 4; ++j) {
        const int co = cg * 4 + j;
        const size_t off = (size_t)(b * 64 + co) * DHW + p0 + pg * 8;
        const float4 xa = __ldg((const float4*)(x + off));
        const float4 xb = __ldg((const float4*)(x + off + 4));
        float4 o0 = make_float4(xa.x * acc[j][0], xa.y * acc[j][1],
                                xa.z * acc[j][2], xa.w * acc[j][3]);
        float4 o1 = make_float4(xb.x * acc[j][4], xb.y * acc[j][5],
                                xb.z * acc[j][6], xb.w * acc[j][7]);
        *(float4*)(out + off)     = o0;
        *(float4*)(out + off + 4) = o1;
    }
}

// ---------------------------------------------------------------------------
extern "C" void kernel_launch(void* const* d_in, const int* in_sizes, int n_in,
                              void* d_out, int out_size)
{
    const float* x  = (const float*)d_in[0];
    const float* w0 = (const float*)d_in[1];
    const float* b0 = (const float*)d_in[2];
    const float* ws = (const float*)d_in[3];
    const float* bs = (const float*)d_in[4];
    const float* w1 = (const float*)d_in[5];
    const float* b1 = (const float*)d_in[6];
    float* out = (float*)d_out;

    dw5_kernel<<<dim3(6, 6, BB * CC), 192>>>(x, w0, b0);
    dw7_kernel<<<dim3(54, CC, BB), 128>>>(ws, bs);
    pw_kernel<<<dim3(DHW / 128, BB), 256>>>(x, w1, b1, out);
}

// round 5
// speedup vs baseline: 1.3694x; 1.0944x over previous
#include <cuda_runtime.h>

#define BB 2
#define CC 64
#define DD 48
#define HH 48
#define WW 48
#define HW (HH*WW)          // 2304
#define DHW (DD*HW)         // 110592
#define TOT (BB*CC*DHW)     // 14155776

__device__ float g_t1[TOT];
__device__ float g_t2[TOT];

// ---------------------------------------------------------------------------
// Kernel 1: depthwise 5x5x5, pad 2.  x -> g_t1
// Block tile: 8z x 8y x 48w. 192 threads = 8ty x 6wg x 4zg.
// Thread: 2z x 8w outputs, scalar FFMA. Rows read as 3x LDS.128.
// Smem: 12 x 12 x 60 floats (stride 60: 15 quads, gcd(15,8)=1 -> conflict-free).
// Prologue: div-free incremental (zi,yi,wi), batched LDG->STS groups of 5.
// Weights padded to stride 8 -> LDS.128 + LDS.32 per (dz,dy) row.
// ---------------------------------------------------------------------------
#define S5 60
__global__ __launch_bounds__(192) void dw5_kernel(
    const float* __restrict__ x,
    const float* __restrict__ w0,
    const float* __restrict__ b0)
{
    __shared__ float sh[12 * 12 * S5];   // 34560 B
    __shared__ float swp[25 * 8];        // padded (dz*5+dy)*8 + dw

    const int z0b = blockIdx.x * 8;
    const int y0  = blockIdx.y * 8;
    const int bc  = blockIdx.z;
    const int c   = bc & 63;
    const int tid = threadIdx.x;

    const float* __restrict__ xin = x + (size_t)bc * DHW;

    // FIX (R4 bug): grid-stride so all 200 padded slots are written by 192 threads
    for (int i = tid; i < 200; i += 192) {
        int p = i >> 3, dw = i & 7;
        swp[i] = (dw < 5) ? w0[c * 125 + p * 5 + dw] : 0.f;
    }

    // div-free tile load: 8640 elems = 45 iters x 192 threads, batches of 5
    {
        int idx = tid;
        int zi = idx / 720;
        int r  = idx - zi * 720;
        int yi = r / S5;
        int wi = r - yi * S5;
        #pragma unroll 1
        for (int ob = 0; ob < 9; ++ob) {
            float vv[5];
            int   si[5];
            #pragma unroll
            for (int u = 0; u < 5; ++u) {
                const int gz = z0b - 2 + zi, gy = y0 - 2 + yi, gw = wi - 2;
                float v = 0.f;
                if ((unsigned)gz < 48u && (unsigned)gy < 48u && (unsigned)gw < 48u)
                    v = xin[gz * HW + gy * WW + gw];
                vv[u] = v; si[u] = idx;
                idx += 192;
                wi += 12; if (wi >= S5) { wi -= S5; ++yi; }
                yi += 3;  if (yi >= 12) { yi -= 12; ++zi; }
            }
            #pragma unroll
            for (int u = 0; u < 5; ++u) sh[si[u]] = vv[u];
        }
    }
    __syncthreads();

    const int ty    = tid & 7;
    const int wg    = (tid >> 3) % 6;
    const int zg    = tid / 48;          // 0..3
    const int wbase = wg * 8;

    const float bias = __ldg(&b0[c]);
    float acc0[8], acc1[8];
    #pragma unroll
    for (int j = 0; j < 8; ++j) { acc0[j] = bias; acc1[j] = bias; }

    #pragma unroll 1
    for (int dy = 0; dy < 5; ++dy) {
        float wb[2][5];
        #pragma unroll
        for (int st = 0; st < 6; ++st) {
            const float4* row4 =
                (const float4*)&sh[((zg * 2 + st) * 12 + ty + dy) * S5 + wbase];
            float4 q0 = row4[0], q1 = row4[1], q2 = row4[2];
            float v[12] = {q0.x,q0.y,q0.z,q0.w, q1.x,q1.y,q1.z,q1.w,
                           q2.x,q2.y,q2.z,q2.w};

            float* wn = wb[st & 1];
            float* wp = wb[(st & 1) ^ 1];

            if (st <= 4) {                       // loz=0: dz = st
                const float4 wa = *(const float4*)&swp[(st * 5 + dy) * 8];
                wn[0] = wa.x; wn[1] = wa.y; wn[2] = wa.z; wn[3] = wa.w;
                wn[4] = swp[(st * 5 + dy) * 8 + 4];
                #pragma unroll
                for (int dw = 0; dw < 5; ++dw) {
                    const float w = wn[dw];
                    #pragma unroll
                    for (int k = 0; k < 8; ++k)
                        acc0[k] += w * v[k + dw];
                }
            }
            if (st >= 1) {                       // loz=1: dz = st-1 (rotated)
                #pragma unroll
                for (int dw = 0; dw < 5; ++dw) {
                    const float w = wp[dw];
                    #pragma unroll
                    for (int k = 0; k < 8; ++k)
                        acc1[k] += w * v[k + dw];
                }
            }
        }
    }

    float* __restrict__ ob = g_t1 + (size_t)bc * DHW;
    #pragma unroll
    for (int loz = 0; loz < 2; ++loz) {
        const float* a = loz ? acc1 : acc0;
        const int gz = z0b + zg * 2 + loz;
        float4* op = (float4*)(ob + gz * HW + (y0 + ty) * WW + wbase);
        op[0] = make_float4(a[0], a[1], a[2], a[3]);
        op[1] = make_float4(a[4], a[5], a[6], a[7]);
    }
}

// ---------------------------------------------------------------------------
// Kernel 2: depthwise 7x7x7, dilation 3, pad 9.  g_t1 -> g_t2
// Residue decomposition into 27 dense 16^3 subgrids (7^3 pad-3 conv each).
// Block: (res*2+zhalf, c, b); 128 threads = 16ty x 2wg x 4zg.
// Thread: 2z x 8w outputs. Rows read as 4x LDS.128.
// Smem: 14 x 22 x 28 floats (stride 28: 7 quads, gcd(7,8)=1 -> conflict-free).
// Prologue: div-free incremental, batched groups of 4.
// Weights padded to stride 8 -> 2x LDS.128 per (dz,dy) row.
// ---------------------------------------------------------------------------
#define S7 28
__global__ __launch_bounds__(128) void dw7_kernel(
    const float* __restrict__ ws,
    const float* __restrict__ bs)
{
    __shared__ float sh[14 * 22 * S7];   // 34496 B
    __shared__ float swp[49 * 8];        // padded (dz*7+dy)*8 + dw

    const int bx    = blockIdx.x;
    const int zhalf = bx & 1;
    const int res   = bx >> 1;
    const int rz = res / 9, ry = (res / 3) % 3, rw = res % 3;
    const int c  = blockIdx.y;
    const int b  = blockIdx.z;
    const int bc = b * 64 + c;
    const int tid = threadIdx.x;

    const float* __restrict__ xin = g_t1 + (size_t)bc * DHW;

    for (int i = tid; i < 392; i += 128) {
        int p = i >> 3, dw = i & 7;
        swp[i] = (dw < 7) ? ws[c * 343 + p * 7 + dw] : 0.f;
    }

    const int zb = zhalf * 8;
    // 8624 elems; 68 iters x 128 threads (guarded), batches of 4
    {
        int idx = tid;
        int zi = idx / 616;
        int r  = idx - zi * 616;
        int yi = r / S7;
        int wi = r - yi * S7;
        #pragma unroll 1
        for (int ob = 0; ob < 17; ++ob) {
            float vv[4];
            int   si[4];
            #pragma unroll
            for (int u = 0; u < 4; ++u) {
                const int sz = zb - 3 + zi, sy = yi - 3, sx = wi - 3;
                float v = 0.f;
                if ((unsigned)sz < 16u && (unsigned)sy < 16u && (unsigned)sx < 16u)
                    v = xin[(3 * sz + rz) * HW + (3 * sy + ry) * WW + (3 * sx + rw)];
                vv[u] = v; si[u] = idx;
                idx += 128;
                wi += 16; if (wi >= S7) { wi -= S7; ++yi; }
                yi += 4;  if (yi >= 22) { yi -= 22; ++zi; }
            }
            #pragma unroll
            for (int u = 0; u < 4; ++u)
                if (si[u] < 8624) sh[si[u]] = vv[u];
        }
    }
    __syncthreads();

    const int ty    = tid & 15;
    const int wg    = (tid >> 4) & 1;
    const int zg    = tid >> 5;          // 0..3
    const int wbase = wg * 8;

    const float bias = __ldg(&bs[c]);
    float acc0[8], acc1[8];
    #pragma unroll
    for (int j = 0; j < 8; ++j) { acc0[j] = bias; acc1[j] = bias; }

    #pragma unroll 1
    for (int dy = 0; dy < 7; ++dy) {
        float wb[2][7];
        #pragma unroll
        for (int st = 0; st < 8; ++st) {
            const float4* row4 =
                (const float4*)&sh[((zg * 2 + st) * 22 + ty + dy) * S7 + wbase];
            float4 q0 = row4[0], q1 = row4[1], q2 = row4[2], q3 = row4[3];
            float v[16] = {q0.x,q0.y,q0.z,q0.w, q1.x,q1.y,q1.z,q1.w,
                           q2.x,q2.y,q2.z,q2.w, q3.x,q3.y,q3.z,q3.w};

            float* wn = wb[st & 1];
            float* wp = wb[(st & 1) ^ 1];

            if (st <= 6) {                      // loz=0: dz = st
                const float4* wq = (const float4*)&swp[(st * 7 + dy) * 8];
                const float4 wa = wq[0], wc = wq[1];
                wn[0] = wa.x; wn[1] = wa.y; wn[2] = wa.z; wn[3] = wa.w;
                wn[4] = wc.x; wn[5] = wc.y; wn[6] = wc.z;
                #pragma unroll
                for (int dw = 0; dw < 7; ++dw) {
                    const float w = wn[dw];
                    #pragma unroll
                    for (int k = 0; k < 8; ++k)
                        acc0[k] += w * v[k + dw];
                }
            }
            if (st >= 1) {                      // loz=1: dz = st-1 (rotated)
                #pragma unroll
                for (int dw = 0; dw < 7; ++dw) {
                    const float w = wp[dw];
                    #pragma unroll
                    for (int k = 0; k < 8; ++k)
                        acc1[k] += w * v[k + dw];
                }
            }
        }
    }

    float* __restrict__ ob = g_t2 + (size_t)bc * DHW;
    #pragma unroll
    for (int loz = 0; loz < 2; ++loz) {
        const float* a = loz ? acc1 : acc0;
        const int gz = 3 * (zb + zg * 2 + loz) + rz;
        const int gy = 3 * ty + ry;
        float* op = ob + gz * HW + gy * WW + rw;
        #pragma unroll
        for (int j = 0; j < 8; ++j)
            op[3 * (wbase + j)] = a[j];
    }
}

// ---------------------------------------------------------------------------
// Kernel 3: pointwise 64x64 conv + bias + gate by x.  g_t2, x -> out
// Block: 128 spatial points x 64 co. 256 threads = 16 pg (8 pts) x 16 cg (4 co).
// Weights transposed in smem: one LDS.128 per ci yields 4 co-weights.
// Per ci iter: 2 LDG.128 + 1 LDS.128 + 32 FFMA.
// ---------------------------------------------------------------------------
__global__ __launch_bounds__(256) void pw_kernel(
    const float* __restrict__ x,
    const float* __restrict__ w1,
    const float* __restrict__ b1,
    float* __restrict__ out)
{
    __shared__ float sWt[64 * 64];       // [ci][co]

    const int p0  = blockIdx.x * 128;
    const int b   = blockIdx.y;
    const int tid = threadIdx.x;

    for (int i = tid; i < 4096; i += 256) {
        int co = i >> 6, ci = i & 63;
        sWt[ci * 64 + co] = w1[i];
    }
    __syncthreads();

    const int pg = tid & 15;      // 16 groups of 8 points
    const int cg = tid >> 4;      // 16 groups of 4 out-channels

    float acc[4][8];
    #pragma unroll
    for (int j = 0; j < 4; ++j) {
        const float bias = __ldg(&b1[cg * 4 + j]);
        #pragma unroll
        for (int k = 0; k < 8; ++k) acc[j][k] = bias;
    }

    const float4* __restrict__ tp =
        (const float4*)(g_t2 + (size_t)b * 64 * DHW + p0) + pg * 2;

    #pragma unroll 4
    for (int ci = 0; ci < 64; ++ci) {
        const float4 A = __ldg(tp + (size_t)ci * (DHW / 4));
        const float4 B = __ldg(tp + (size_t)ci * (DHW / 4) + 1);
        const float4 wv = *(const float4*)&sWt[ci * 64 + cg * 4];
        const float w4[4] = {wv.x, wv.y, wv.z, wv.w};
        #pragma unroll
        for (int j = 0; j < 4; ++j) {
            const float w = w4[j];
            acc[j][0] += w * A.x;  acc[j][1] += w * A.y;
            acc[j][2] += w * A.z;  acc[j][3] += w * A.w;
            acc[j][4] += w * B.x;  acc[j][5] += w * B.y;
            acc[j][6] += w * B.z;  acc[j][7] += w * B.w;
        }
    }

    #pragma unroll
    for (int j = 0; j < 4; ++j) {
        const int co = cg * 4 + j;
        const size_t off = (size_t)(b * 64 + co) * DHW + p0 + pg * 8;
        const float4 xa = __ldg((const float4*)(x + off));
        const float4 xb = __ldg((const float4*)(x + off + 4));
        float4 o0 = make_float4(xa.x * acc[j][0], xa.y * acc[j][1],
                                xa.z * acc[j][2], xa.w * acc[j][3]);
        float4 o1 = make_float4(xb.x * acc[j][4], xb.y * acc[j][5],
                                xb.z * acc[j][6], xb.w * acc[j][7]);
        *(float4*)(out + off)     = o0;
        *(float4*)(out + off + 4) = o1;
    }
}

// ---------------------------------------------------------------------------
extern "C" void kernel_launch(void* const* d_in, const int* in_sizes, int n_in,
                              void* d_out, int out_size)
{
    const float* x  = (const float*)d_in[0];
    const float* w0 = (const float*)d_in[1];
    const float* b0 = (const float*)d_in[2];
    const float* ws = (const float*)d_in[3];
    const float* bs = (const float*)d_in[4];
    const float* w1 = (const float*)d_in[5];
    const float* b1 = (const float*)d_in[6];
    float* out = (float*)d_out;

    dw5_kernel<<<dim3(6, 6, BB * CC), 192>>>(x, w0, b0);
    dw7_kernel<<<dim3(54, CC, BB), 128>>>(ws, bs);
    pw_kernel<<<dim3(DHW / 128, BB), 256>>>(x, w1, b1, out);
}

// round 7
// speedup vs baseline: 1.5807x; 1.1543x over previous
#include <cuda_runtime.h>

#define BB 2
#define CC 64
#define DD 48
#define HH 48
#define WW 48
#define HW (HH*WW)          // 2304
#define DHW (DD*HW)         // 110592
#define TOT (BB*CC*DHW)     // 14155776

__device__ float g_t1[TOT];
__device__ float g_t2[TOT];

// ---------------------------------------------------------------------------
// Kernel 1: depthwise 5x5x5, pad 2.  x -> g_t1
// Block tile: 12z x 8y x 48w. 288 threads = 8ty x 6wg x 6zg.
// Thread: 2z x 8w outputs, scalar FFMA. Rows read as 3x LDS.128.
// Smem: 16 x 12 x 60 floats = 46.1KB static (stride 60 -> conflict-free).
// Prologue: ROW-WISE load: 192 rows, 1 row/thread. Bounds once per row,
//           12x LDG.128 + STS.64 writes (w-halo zeros compile-time).
// ---------------------------------------------------------------------------
#define S5 60
__global__ __launch_bounds__(288) void dw5_kernel(
    const float* __restrict__ x,
    const float* __restrict__ w0,
    const float* __restrict__ b0)
{
    __shared__ float sh[16 * 12 * S5];   // 46080 B
    __shared__ float swp[25 * 8];        // padded (dz*5+dy)*8 + dw

    const int z0b = blockIdx.x * 12;
    const int y0  = blockIdx.y * 8;
    const int bc  = blockIdx.z;
    const int c   = bc & 63;
    const int tid = threadIdx.x;

    const float* __restrict__ xin = x + (size_t)bc * DHW;

    if (tid < 200) {
        int p = tid >> 3, dw = tid & 7;
        swp[tid] = (dw < 5) ? w0[c * 125 + p * 5 + dw] : 0.f;
    }

    // Row-wise tile load: 192 rows (16 planes x 12 y), one row per thread.
    if (tid < 192) {
        const int p  = tid / 12;         // plane 0..15
        const int yi = tid - p * 12;     // 0..11
        const int gz = z0b - 2 + p;
        const int gy = y0 - 2 + yi;
        float* __restrict__ dst = &sh[tid * S5];
        if ((unsigned)gz < 48u && (unsigned)gy < 48u) {
            const float4* __restrict__ src =
                (const float4*)(xin + gz * HW + gy * WW);
            float4 q[12];
            #pragma unroll
            for (int i = 0; i < 12; ++i) q[i] = src[i];
            *(float2*)(dst) = make_float2(0.f, 0.f);
            #pragma unroll
            for (int i = 0; i < 12; ++i) {
                *(float2*)(dst + 2 + 4 * i)     = make_float2(q[i].x, q[i].y);
                *(float2*)(dst + 2 + 4 * i + 2) = make_float2(q[i].z, q[i].w);
            }
            #pragma unroll
            for (int i = 0; i < 5; ++i)
                *(float2*)(dst + 50 + 2 * i) = make_float2(0.f, 0.f);
        } else {
            #pragma unroll
            for (int i = 0; i < 15; ++i)
                *(float4*)(dst + 4 * i) = make_float4(0.f, 0.f, 0.f, 0.f);
        }
    }
    __syncthreads();

    const int ty    = tid & 7;
    const int wg    = (tid >> 3) % 6;
    const int zg    = tid / 48;          // 0..5
    const int wbase = wg * 8;

    const float bias = __ldg(&b0[c]);
    float acc0[8], acc1[8];
    #pragma unroll
    for (int j = 0; j < 8; ++j) { acc0[j] = bias; acc1[j] = bias; }

    #pragma unroll 1
    for (int dy = 0; dy < 5; ++dy) {
        float wb[2][5];
        #pragma unroll
        for (int st = 0; st < 6; ++st) {
            const float4* row4 =
                (const float4*)&sh[((zg * 2 + st) * 12 + ty + dy) * S5 + wbase];
            float4 q0 = row4[0], q1 = row4[1], q2 = row4[2];
            float v[12] = {q0.x,q0.y,q0.z,q0.w, q1.x,q1.y,q1.z,q1.w,
                           q2.x,q2.y,q2.z,q2.w};

            float* wn = wb[st & 1];
            float* wp = wb[(st & 1) ^ 1];

            if (st <= 4) {                       // loz=0: dz = st
                const float4 wa = *(const float4*)&swp[(st * 5 + dy) * 8];
                wn[0] = wa.x; wn[1] = wa.y; wn[2] = wa.z; wn[3] = wa.w;
                wn[4] = swp[(st * 5 + dy) * 8 + 4];
                #pragma unroll
                for (int dw = 0; dw < 5; ++dw) {
                    const float w = wn[dw];
                    #pragma unroll
                    for (int k = 0; k < 8; ++k)
                        acc0[k] += w * v[k + dw];
                }
            }
            if (st >= 1) {                       // loz=1: dz = st-1 (rotated)
                #pragma unroll
                for (int dw = 0; dw < 5; ++dw) {
                    const float w = wp[dw];
                    #pragma unroll
                    for (int k = 0; k < 8; ++k)
                        acc1[k] += w * v[k + dw];
                }
            }
        }
    }

    float* __restrict__ ob = g_t1 + (size_t)bc * DHW;
    #pragma unroll
    for (int loz = 0; loz < 2; ++loz) {
        const float* a = loz ? acc1 : acc0;
        const int gz = z0b + zg * 2 + loz;
        float4* op = (float4*)(ob + gz * HW + (y0 + ty) * WW + wbase);
        op[0] = make_float4(a[0], a[1], a[2], a[3]);
        op[1] = make_float4(a[4], a[5], a[6], a[7]);
    }
}

// ---------------------------------------------------------------------------
// Kernel 2: depthwise 7x7x7, dilation 3, pad 9.  g_t1 -> g_t2
// Residue decomposition into 27 dense 16^3 subgrids (7^3 pad-3 conv each).
// Block: (res*2+zhalf, c, b); 128 threads = 16ty x 2wg x 4zg.
// Thread: 2z x 8w outputs. Rows read as 4x LDS.128.
// Smem: 14 x 22 x 28 floats = 34.5KB STATIC (no attribute calls).
// Prologue: ROW-WISE: 308 rows (14 planes x 22 y), <=3 rows/thread;
//           16 strided LDG + 7 STS.128 per row, bounds once per row.
// ---------------------------------------------------------------------------
#define S7 28
__global__ __launch_bounds__(128) void dw7_kernel(
    const float* __restrict__ ws,
    const float* __restrict__ bs)
{
    __shared__ float sh[14 * 22 * S7];   // 34496 B
    __shared__ float swp[49 * 8];        // padded (dz*7+dy)*8 + dw

    const int bx    = blockIdx.x;
    const int zhalf = bx & 1;
    const int res   = bx >> 1;
    const int rz = res / 9, ry = (res / 3) % 3, rw = res % 3;
    const int c  = blockIdx.y;
    const int b  = blockIdx.z;
    const int bc = b * 64 + c;
    const int tid = threadIdx.x;

    const float* __restrict__ xin = g_t1 + (size_t)bc * DHW;

    for (int i = tid; i < 392; i += 128) {
        int p = i >> 3, dw = i & 7;
        swp[i] = (dw < 7) ? ws[c * 343 + p * 7 + dw] : 0.f;
    }

    const int zb = zhalf * 8;
    // Row-wise tile load: 308 rows (14 planes x 22 y), 128 threads.
    #pragma unroll
    for (int rr = 0; rr < 3; ++rr) {
        const int r = tid + rr * 128;
        if (r < 308) {
            const int p  = r / 22;           // plane 0..13
            const int yi = r - p * 22;       // 0..21
            const int sz = zb - 3 + p;       // subgrid z
            const int sy = yi - 3;
            float* __restrict__ dst = &sh[r * S7];
            if ((unsigned)sz < 16u && (unsigned)sy < 16u) {
                const float* __restrict__ src =
                    xin + (3 * sz + rz) * HW + (3 * sy + ry) * WW + rw;
                float d[16];
                #pragma unroll
                for (int j = 0; j < 16; ++j) d[j] = src[3 * j];
                float4* __restrict__ dq = (float4*)dst;
                dq[0] = make_float4(0.f, 0.f, 0.f, d[0]);
                dq[1] = make_float4(d[1], d[2], d[3], d[4]);
                dq[2] = make_float4(d[5], d[6], d[7], d[8]);
                dq[3] = make_float4(d[9], d[10], d[11], d[12]);
                dq[4] = make_float4(d[13], d[14], d[15], 0.f);
                dq[5] = make_float4(0.f, 0.f, 0.f, 0.f);
                dq[6] = make_float4(0.f, 0.f, 0.f, 0.f);
            } else {
                float4* __restrict__ dq = (float4*)dst;
                #pragma unroll
                for (int i = 0; i < 7; ++i)
                    dq[i] = make_float4(0.f, 0.f, 0.f, 0.f);
            }
        }
    }
    __syncthreads();

    const int ty    = tid & 15;
    const int wg    = (tid >> 4) & 1;
    const int zg    = tid >> 5;          // 0..3
    const int wbase = wg * 8;

    const float bias = __ldg(&bs[c]);
    float acc0[8], acc1[8];
    #pragma unroll
    for (int j = 0; j < 8; ++j) { acc0[j] = bias; acc1[j] = bias; }

    #pragma unroll 1
    for (int dy = 0; dy < 7; ++dy) {
        float wb[2][7];
        #pragma unroll
        for (int st = 0; st < 8; ++st) {
            const float4* row4 =
                (const float4*)&sh[((zg * 2 + st) * 22 + ty + dy) * S7 + wbase];
            float4 q0 = row4[0], q1 = row4[1], q2 = row4[2], q3 = row4[3];
            float v[16] = {q0.x,q0.y,q0.z,q0.w, q1.x,q1.y,q1.z,q1.w,
                           q2.x,q2.y,q2.z,q2.w, q3.x,q3.y,q3.z,q3.w};

            float* wn = wb[st & 1];
            float* wp = wb[(st & 1) ^ 1];

            if (st <= 6) {                      // loz=0: dz = st
                const float4* wq = (const float4*)&swp[(st * 7 + dy) * 8];
                const float4 wa = wq[0], wc = wq[1];
                wn[0] = wa.x; wn[1] = wa.y; wn[2] = wa.z; wn[3] = wa.w;
                wn[4] = wc.x; wn[5] = wc.y; wn[6] = wc.z;
                #pragma unroll
                for (int dw = 0; dw < 7; ++dw) {
                    const float w = wn[dw];
                    #pragma unroll
                    for (int k = 0; k < 8; ++k)
                        acc0[k] += w * v[k + dw];
                }
            }
            if (st >= 1) {                      // loz=1: dz = st-1 (rotated)
                #pragma unroll
                for (int dw = 0; dw < 7; ++dw) {
                    const float w = wp[dw];
                    #pragma unroll
                    for (int k = 0; k < 8; ++k)
                        acc1[k] += w * v[k + dw];
                }
            }
        }
    }

    float* __restrict__ ob = g_t2 + (size_t)bc * DHW;
    #pragma unroll
    for (int loz = 0; loz < 2; ++loz) {
        const float* a = loz ? acc1 : acc0;
        const int gz = 3 * (zb + zg * 2 + loz) + rz;
        const int gy = 3 * ty + ry;
        float* op = ob + gz * HW + gy * WW + rw;
        #pragma unroll
        for (int j = 0; j < 8; ++j)
            op[3 * (wbase + j)] = a[j];
    }
}

// ---------------------------------------------------------------------------
// Kernel 3: pointwise 64x64 conv + bias + gate by x.  g_t2, x -> out
// Block: 128 spatial points x 64 co. 256 threads = 16 pg (8 pts) x 16 cg (4 co).
// Weights transposed in smem: one LDS.128 per ci yields 4 co-weights.
// Per ci iter: 2 LDG.128 + 1 LDS.128 + 32 FFMA.
// ---------------------------------------------------------------------------
__global__ __launch_bounds__(256) void pw_kernel(
    const float* __restrict__ x,
    const float* __restrict__ w1,
    const float* __restrict__ b1,
    float* __restrict__ out)
{
    __shared__ float sWt[64 * 64];       // [ci][co]

    const int p0  = blockIdx.x * 128;
    const int b   = blockIdx.y;
    const int tid = threadIdx.x;

    for (int i = tid; i < 4096; i += 256) {
        int co = i >> 6, ci = i & 63;
        sWt[ci * 64 + co] = w1[i];
    }
    __syncthreads();

    const int pg = tid & 15;      // 16 groups of 8 points
    const int cg = tid >> 4;      // 16 groups of 4 out-channels

    float acc[4][8];
    #pragma unroll
    for (int j = 0; j < 4; ++j) {
        const float bias = __ldg(&b1[cg * 4 + j]);
        #pragma unroll
        for (int k = 0; k < 8; ++k) acc[j][k] = bias;
    }

    const float4* __restrict__ tp =
        (const float4*)(g_t2 + (size_t)b * 64 * DHW + p0) + pg * 2;

    #pragma unroll 4
    for (int ci = 0; ci < 64; ++ci) {
        const float4 A = __ldg(tp + (size_t)ci * (DHW / 4));
        const float4 B = __ldg(tp + (size_t)ci * (DHW / 4) + 1);
        const float4 wv = *(const float4*)&sWt[ci * 64 + cg * 4];
        const float w4[4] = {wv.x, wv.y, wv.z, wv.w};
        #pragma unroll
        for (int j = 0; j < 4; ++j) {
            const float w = w4[j];
            acc[j][0] += w * A.x;  acc[j][1] += w * A.y;
            acc[j][2] += w * A.z;  acc[j][3] += w * A.w;
            acc[j][4] += w * B.x;  acc[j][5] += w * B.y;
            acc[j][6] += w * B.z;  acc[j][7] += w * B.w;
        }
    }

    #pragma unroll
    for (int j = 0; j < 4; ++j) {
        const int co = cg * 4 + j;
        const size_t off = (size_t)(b * 64 + co) * DHW + p0 + pg * 8;
        const float4 xa = __ldg((const float4*)(x + off));
        const float4 xb = __ldg((const float4*)(x + off + 4));
        float4 o0 = make_float4(xa.x * acc[j][0], xa.y * acc[j][1],
                                xa.z * acc[j][2], xa.w * acc[j][3]);
        float4 o1 = make_float4(xb.x * acc[j][4], xb.y * acc[j][5],
                                xb.z * acc[j][6], xb.w * acc[j][7]);
        *(float4*)(out + off)     = o0;
        *(float4*)(out + off + 4) = o1;
    }
}

// ---------------------------------------------------------------------------
extern "C" void kernel_launch(void* const* d_in, const int* in_sizes, int n_in,
                              void* d_out, int out_size)
{
    const float* x  = (const float*)d_in[0];
    const float* w0 = (const float*)d_in[1];
    const float* b0 = (const float*)d_in[2];
    const float* ws = (const float*)d_in[3];
    const float* bs = (const float*)d_in[4];
    const float* w1 = (const float*)d_in[5];
    const float* b1 = (const float*)d_in[6];
    float* out = (float*)d_out;

    dw5_kernel<<<dim3(4, 6, BB * CC), 288>>>(x, w0, b0);
    dw7_kernel<<<dim3(54, CC, BB), 128>>>(ws, bs);
    pw_kernel<<<dim3(DHW / 128, BB), 256>>>(x, w1, b1, out);
}

// round 8
// speedup vs baseline: 1.6236x; 1.0271x over previous
#include <cuda_runtime.h>

#define BB 2
#define CC 64
#define DD 48
#define HH 48
#define WW 48
#define HW (HH*WW)          // 2304
#define DHW (DD*HW)         // 110592
#define TOT (BB*CC*DHW)     // 14155776

__device__ float g_t1[TOT];
__device__ float g_t2[TOT];

// ---------------------------------------------------------------------------
// Kernel 1: depthwise 5x5x5, pad 2.  x -> g_t1
// Block tile: 12z x 8y x 48w. 144 threads = 8ty x 6wg x 3zg.
// Thread: 4z x 8w outputs (depth-4 weight-row rotation). Rows as 3x LDS.128.
// Smem: 16 x 12 x 60 floats = 46.1KB static (conflict-free phases).
// Prologue: row-wise, bounds once per row.
// ---------------------------------------------------------------------------
#define S5 60
__global__ __launch_bounds__(144) void dw5_kernel(
    const float* __restrict__ x,
    const float* __restrict__ w0,
    const float* __restrict__ b0)
{
    __shared__ float sh[16 * 12 * S5];   // 46080 B
    __shared__ float swp[25 * 8];        // padded (dz*5+dy)*8 + dw

    const int z0b = blockIdx.x * 12;
    const int y0  = blockIdx.y * 8;
    const int bc  = blockIdx.z;
    const int c   = bc & 63;
    const int tid = threadIdx.x;

    const float* __restrict__ xin = x + (size_t)bc * DHW;

    for (int i = tid; i < 200; i += 144) {
        int p = i >> 3, dw = i & 7;
        swp[i] = (dw < 5) ? w0[c * 125 + p * 5 + dw] : 0.f;
    }

    // Row-wise tile load: 192 rows (16 planes x 12 y).
    #pragma unroll
    for (int rr = 0; rr < 2; ++rr) {
        const int r = tid + rr * 144;
        if (r < 192) {
            const int p  = r / 12;
            const int yi = r - p * 12;
            const int gz = z0b - 2 + p;
            const int gy = y0 - 2 + yi;
            float* __restrict__ dst = &sh[r * S5];
            if ((unsigned)gz < 48u && (unsigned)gy < 48u) {
                const float4* __restrict__ src =
                    (const float4*)(xin + gz * HW + gy * WW);
                float4 q[12];
                #pragma unroll
                for (int i = 0; i < 12; ++i) q[i] = src[i];
                *(float2*)(dst) = make_float2(0.f, 0.f);
                #pragma unroll
                for (int i = 0; i < 12; ++i) {
                    *(float2*)(dst + 2 + 4 * i)     = make_float2(q[i].x, q[i].y);
                    *(float2*)(dst + 2 + 4 * i + 2) = make_float2(q[i].z, q[i].w);
                }
                #pragma unroll
                for (int i = 0; i < 5; ++i)
                    *(float2*)(dst + 50 + 2 * i) = make_float2(0.f, 0.f);
            } else {
                #pragma unroll
                for (int i = 0; i < 15; ++i)
                    *(float4*)(dst + 4 * i) = make_float4(0.f, 0.f, 0.f, 0.f);
            }
        }
    }
    __syncthreads();

    const int ty    = tid & 7;
    const int wg    = (tid >> 3) % 6;
    const int zg    = tid / 48;          // 0..2
    const int wbase = wg * 8;

    const float bias = __ldg(&b0[c]);
    float acc[4][8];
    #pragma unroll
    for (int j = 0; j < 4; ++j)
        #pragma unroll
        for (int k = 0; k < 8; ++k) acc[j][k] = bias;

    #pragma unroll 1
    for (int dy = 0; dy < 5; ++dy) {
        float wb[4][5];
        #pragma unroll
        for (int st = 0; st < 8; ++st) {
            const float4* row4 =
                (const float4*)&sh[((zg * 4 + st) * 12 + ty + dy) * S5 + wbase];
            float4 q0 = row4[0], q1 = row4[1], q2 = row4[2];
            float v[12] = {q0.x,q0.y,q0.z,q0.w, q1.x,q1.y,q1.z,q1.w,
                           q2.x,q2.y,q2.z,q2.w};

            if (st <= 4) {   // load weight row dz=st into rotation slot
                const float4 wa = *(const float4*)&swp[(st * 5 + dy) * 8];
                float* wn = wb[st & 3];
                wn[0] = wa.x; wn[1] = wa.y; wn[2] = wa.z; wn[3] = wa.w;
                wn[4] = swp[(st * 5 + dy) * 8 + 4];
            }
            #pragma unroll
            for (int j = 0; j < 4; ++j) {
                if (st - j >= 0 && st - j <= 4) {   // compile-time
                    const float* w = wb[(st - j) & 3];
                    #pragma unroll
                    for (int dw = 0; dw < 5; ++dw) {
                        const float wv = w[dw];
                        #pragma unroll
                        for (int k = 0; k < 8; ++k)
                            acc[j][k] += wv * v[k + dw];
                    }
                }
            }
        }
    }

    float* __restrict__ ob = g_t1 + (size_t)bc * DHW;
    #pragma unroll
    for (int j = 0; j < 4; ++j) {
        const int gz = z0b + zg * 4 + j;
        float4* op = (float4*)(ob + gz * HW + (y0 + ty) * WW + wbase);
        op[0] = make_float4(acc[j][0], acc[j][1], acc[j][2], acc[j][3]);
        op[1] = make_float4(acc[j][4], acc[j][5], acc[j][6], acc[j][7]);
    }
}

// ---------------------------------------------------------------------------
// Kernel 2: depthwise 7x7x7, dilation 3, pad 9.  g_t1 -> g_t2
// Residue decomposition into 27 dense 16^3 subgrids (7^3 pad-3 conv each).
// Block: (res*2+zhalf, c, b); 64 threads = 16ty x 2wg x 2zg.
// Thread: 4z x 8w outputs, depth-4 weight rotation. Rows as 4x LDS.128.
// Smem: 14 x 22 x 28 = 34.5KB static. Prologue row-wise.
// ---------------------------------------------------------------------------
#define S7 28
__global__ __launch_bounds__(64) void dw7_kernel(
    const float* __restrict__ ws,
    const float* __restrict__ bs)
{
    __shared__ float sh[14 * 22 * S7];   // 34496 B
    __shared__ float swp[49 * 8];        // padded (dz*7+dy)*8 + dw

    const int bx    = blockIdx.x;
    const int zhalf = bx & 1;
    const int res   = bx >> 1;
    const int rz = res / 9, ry = (res / 3) % 3, rw = res % 3;
    const int c  = blockIdx.y;
    const int b  = blockIdx.z;
    const int bc = b * 64 + c;
    const int tid = threadIdx.x;

    const float* __restrict__ xin = g_t1 + (size_t)bc * DHW;

    for (int i = tid; i < 392; i += 64) {
        int p = i >> 3, dw = i & 7;
        swp[i] = (dw < 7) ? ws[c * 343 + p * 7 + dw] : 0.f;
    }

    const int zb = zhalf * 8;
    // Row-wise tile load: 308 rows (14 planes x 22 y), 64 threads.
    #pragma unroll
    for (int rr = 0; rr < 5; ++rr) {
        const int r = tid + rr * 64;
        if (r < 308) {
            const int p  = r / 22;
            const int yi = r - p * 22;
            const int sz = zb - 3 + p;
            const int sy = yi - 3;
            float* __restrict__ dst = &sh[r * S7];
            if ((unsigned)sz < 16u && (unsigned)sy < 16u) {
                const float* __restrict__ src =
                    xin + (3 * sz + rz) * HW + (3 * sy + ry) * WW + rw;
                float d[16];
                #pragma unroll
                for (int j = 0; j < 16; ++j) d[j] = src[3 * j];
                float4* __restrict__ dq = (float4*)dst;
                dq[0] = make_float4(0.f, 0.f, 0.f, d[0]);
                dq[1] = make_float4(d[1], d[2], d[3], d[4]);
                dq[2] = make_float4(d[5], d[6], d[7], d[8]);
                dq[3] = make_float4(d[9], d[10], d[11], d[12]);
                dq[4] = make_float4(d[13], d[14], d[15], 0.f);
                dq[5] = make_float4(0.f, 0.f, 0.f, 0.f);
                dq[6] = make_float4(0.f, 0.f, 0.f, 0.f);
            } else {
                float4* __restrict__ dq = (float4*)dst;
                #pragma unroll
                for (int i = 0; i < 7; ++i)
                    dq[i] = make_float4(0.f, 0.f, 0.f, 0.f);
            }
        }
    }
    __syncthreads();

    const int ty    = tid & 15;
    const int wg    = (tid >> 4) & 1;
    const int zg    = tid >> 5;          // 0..1
    const int wbase = wg * 8;

    const float bias = __ldg(&bs[c]);
    float acc[4][8];
    #pragma unroll
    for (int j = 0; j < 4; ++j)
        #pragma unroll
        for (int k = 0; k < 8; ++k) acc[j][k] = bias;

    #pragma unroll 1
    for (int dy = 0; dy < 7; ++dy) {
        float wb[4][7];
        #pragma unroll
        for (int st = 0; st < 10; ++st) {
            const float4* row4 =
                (const float4*)&sh[((zg * 4 + st) * 22 + ty + dy) * S7 + wbase];
            float4 q0 = row4[0], q1 = row4[1], q2 = row4[2], q3 = row4[3];
            float v[16] = {q0.x,q0.y,q0.z,q0.w, q1.x,q1.y,q1.z,q1.w,
                           q2.x,q2.y,q2.z,q2.w, q3.x,q3.y,q3.z,q3.w};

            if (st <= 6) {   // load weight row dz=st into rotation slot
                const float4* wq = (const float4*)&swp[(st * 7 + dy) * 8];
                const float4 wa = wq[0], wc = wq[1];
                float* wn = wb[st & 3];
                wn[0] = wa.x; wn[1] = wa.y; wn[2] = wa.z; wn[3] = wa.w;
                wn[4] = wc.x; wn[5] = wc.y; wn[6] = wc.z;
            }
            #pragma unroll
            for (int j = 0; j < 4; ++j) {
                if (st - j >= 0 && st - j <= 6) {   // compile-time
                    const float* w = wb[(st - j) & 3];
                    #pragma unroll
                    for (int dw = 0; dw < 7; ++dw) {
                        const float wv = w[dw];
                        #pragma unroll
                        for (int k = 0; k < 8; ++k)
                            acc[j][k] += wv * v[k + dw];
                    }
                }
            }
        }
    }

    float* __restrict__ ob = g_t2 + (size_t)bc * DHW;
    #pragma unroll
    for (int j = 0; j < 4; ++j) {
        const int sz = zb + zg * 4 + j;       // 0..15
        const int gz = 3 * sz + rz;
        const int gy = 3 * ty + ry;
        float* op = ob + gz * HW + gy * WW + rw;
        #pragma unroll
        for (int k = 0; k < 8; ++k)
            op[3 * (wbase + k)] = acc[j][k];
    }
}

// ---------------------------------------------------------------------------
// Kernel 3: pointwise 64x64 conv + bias + gate by x.  g_t2, x -> out
// Block: 128 points x 64 co. 128 threads = 16 pg (8 pts) x 8 cg (8 co).
// Per ci: 2 LDG.128 (t2, L1 reuse) + 2 broadcast LDS.128 (8 co wt) + 64 FFMA.
// ---------------------------------------------------------------------------
__global__ __launch_bounds__(128) void pw_kernel(
    const float* __restrict__ x,
    const float* __restrict__ w1,
    const float* __restrict__ b1,
    float* __restrict__ out)
{
    __shared__ float sWt[64 * 64];       // [ci][co]

    const int p0  = blockIdx.x * 128;
    const int b   = blockIdx.y;
    const int tid = threadIdx.x;

    for (int i = tid; i < 4096; i += 128) {
        int co = i >> 6, ci = i & 63;
        sWt[ci * 64 + co] = w1[i];
    }
    __syncthreads();

    const int pg = tid & 15;      // 16 groups of 8 points
    const int cg = tid >> 4;      // 8 groups of 8 out-channels

    float acc[8][8];
    #pragma unroll
    for (int j = 0; j < 8; ++j) {
        const float bias = __ldg(&b1[cg * 8 + j]);
        #pragma unroll
        for (int k = 0; k < 8; ++k) acc[j][k] = bias;
    }

    const float4* __restrict__ tp =
        (const float4*)(g_t2 + (size_t)b * 64 * DHW + p0) + pg * 2;

    #pragma unroll 2
    for (int ci = 0; ci < 64; ++ci) {
        const float4 A = __ldg(tp + (size_t)ci * (DHW / 4));
        const float4 B = __ldg(tp + (size_t)ci * (DHW / 4) + 1);
        const float4* wq = (const float4*)&sWt[ci * 64 + cg * 8];
        const float4 w0v = wq[0], w1v = wq[1];
        const float w8[8] = {w0v.x, w0v.y, w0v.z, w0v.w,
                             w1v.x, w1v.y, w1v.z, w1v.w};
        #pragma unroll
        for (int j = 0; j < 8; ++j) {
            const float w = w8[j];
            acc[j][0] += w * A.x;  acc[j][1] += w * A.y;
            acc[j][2] += w * A.z;  acc[j][3] += w * A.w;
            acc[j][4] += w * B.x;  acc[j][5] += w * B.y;
            acc[j][6] += w * B.z;  acc[j][7] += w * B.w;
        }
    }

    #pragma unroll
    for (int j = 0; j < 8; ++j) {
        const int co = cg * 8 + j;
        const size_t off = (size_t)(b * 64 + co) * DHW + p0 + pg * 8;
        const float4 xa = __ldg((const float4*)(x + off));
        const float4 xb = __ldg((const float4*)(x + off + 4));
        float4 o0 = make_float4(xa.x * acc[j][0], xa.y * acc[j][1],
                                xa.z * acc[j][2], xa.w * acc[j][3]);
        float4 o1 = make_float4(xb.x * acc[j][4], xb.y * acc[j][5],
                                xb.z * acc[j][6], xb.w * acc[j][7]);
        *(float4*)(out + off)     = o0;
        *(float4*)(out + off + 4) = o1;
    }
}

// ---------------------------------------------------------------------------
extern "C" void kernel_launch(void* const* d_in, const int* in_sizes, int n_in,
                              void* d_out, int out_size)
{
    const float* x  = (const float*)d_in[0];
    const float* w0 = (const float*)d_in[1];
    const float* b0 = (const float*)d_in[2];
    const float* ws = (const float*)d_in[3];
    const float* bs = (const float*)d_in[4];
    const float* w1 = (const float*)d_in[5];
    const float* b1 = (const float*)d_in[6];
    float* out = (float*)d_out;

    dw5_kernel<<<dim3(4, 6, BB * CC), 144>>>(x, w0, b0);
    dw7_kernel<<<dim3(54, CC, BB), 64>>>(ws, bs);
    pw_kernel<<<dim3(DHW / 128, BB), 128>>>(x, w1, b1, out);
}